// round 15
// baseline (speedup 1.0000x reference)
#include <cuda_runtime.h>
#include <cstdint>

#define N_NODES 13
#define N_REAL  12
#define BB      4
#define CC      3
#define HH      256
#define WW      256
#define EE      37
#define HWSZ    (HH*WW)

#define PROW 132
#define ROWB (PROW*8)
#define PSTR 259                       // padded rows per plane: 1 + 256 + 2
#define NPLANES (N_NODES*BB*CC)
#define TROWS 11
#define PLANE_F2 (TROWS*PROW)
#define PLANE_BYTES (PLANE_F2*8)       // 11616 B
#define NSLOT 4
#define DYN_BYTES (NSLOT*PLANE_BYTES)  // 46464 B
#define NTILES 1536
#define NCTA 592
typedef unsigned long long ull;

__device__ __align__(16) float2 g_pk[(size_t)NPLANES*PSTR*PROW];
__device__ float2 g_wpk[EE*144];
__device__ int    g_deg[N_REAL];
__device__ int    g_esr[N_REAL][4];
__device__ int    g_eid[N_REAL][4];
__device__ float  g_bsum[N_REAL][3];
__device__ unsigned g_ctr;

__device__ __forceinline__ void upk2(ull v, float& lo, float& hi){
  asm("mov.b64 {%0, %1}, %2;" : "=f"(lo), "=f"(hi) : "l"(v));
}
__device__ __forceinline__ ull ffma2(ull a, ull b, ull c){
  ull d; asm("fma.rn.f32x2 %0, %1, %2, %3;" : "=l"(d) : "l"(a), "l"(b), "l"(c));
  return d;
}
__device__ __forceinline__ float sigf(float x){
  return __fdividef(1.f, 1.f + __expf(-x));
}
__device__ __forceinline__ void mbar_init(uint32_t bar, uint32_t cnt){
  asm volatile("mbarrier.init.shared.b64 [%0], %1;" :: "r"(bar), "r"(cnt) : "memory");
}
__device__ __forceinline__ void mbar_expect_tx(uint32_t bar, uint32_t n){
  asm volatile("mbarrier.arrive.expect_tx.shared.b64 _, [%0], %1;"
               :: "r"(bar), "r"(n) : "memory");
}
__device__ __forceinline__ void mbar_arrive(uint32_t bar){
  asm volatile("mbarrier.arrive.shared.b64 _, [%0];" :: "r"(bar) : "memory");
}
__device__ __forceinline__ void tma_bulk(uint32_t dst, const void* src,
                                         uint32_t n, uint32_t bar){
  asm volatile("cp.async.bulk.shared::cta.global.mbarrier::complete_tx::bytes "
               "[%0], [%1], %2, [%3];"
               :: "r"(dst), "l"(src), "r"(n), "r"(bar) : "memory");
}
__device__ __forceinline__ void mbar_wait(uint32_t bar, uint32_t parity){
  asm volatile(
      "{\n\t.reg .pred P;\n\t"
      "WAIT_%=:\n\t"
      "mbarrier.try_wait.parity.acquire.cta.shared::cta.b64 P, [%0], %1, 0x989680;\n\t"
      "@P bra.uni DONE_%=;\n\t"
      "bra.uni WAIT_%=;\n\t"
      "DONE_%=:\n\t}"
      :: "r"(bar), "r"(parity) : "memory");
}

// ---------- pass 1: setup + sigmoid pack + pads (same as R14) ----------
#define MAIN_BLKS ((N_NODES*BB*CC*HH*32)/256)
#define PAD_F2   (NPLANES*3*PROW)
#define PAD_BLKS ((PAD_F2 + 255)/256)

__global__ void sigmoid_pack_all(const float* __restrict__ x,
                                 const float* __restrict__ Wt,
                                 const float* __restrict__ Bs,
                                 const int*   __restrict__ esrc,
                                 const int*   __restrict__ edst){
  if (blockIdx.x == 0){
    int t = threadIdx.x;
    for (int i=t; i<EE*144; i+=256){ float w=__ldg(&Wt[i]); g_wpk[i]=make_float2(w,w); }
    if (t < N_REAL){
      int d=0; float b0=0.f,b1=0.f,b2=0.f;
      for (int e=0; e<EE; e++)
        if (__ldg(&edst[e]) == t){
          g_esr[t][d]=__ldg(&esrc[e]); g_eid[t][d]=e;
          b0+=__ldg(&Bs[e*3+0]); b1+=__ldg(&Bs[e*3+1]); b2+=__ldg(&Bs[e*3+2]);
          d++;
        }
      g_deg[t]=d; g_bsum[t][0]=b0; g_bsum[t][1]=b1; g_bsum[t][2]=b2;
    }
    if (t == 0) g_ctr = 0u;
    return;
  }
  if (blockIdx.x <= MAIN_BLKS){
    int idx = (blockIdx.x-1)*256 + threadIdx.x;
    int rid = idx >> 5, q = idx & 31;
    const float4* in4 = (const float4*)(x + (size_t)rid*WW);
    float4 lo = __ldg(in4 + q);
    float4 hi = __ldg(in4 + q + 32);
    float slx=sigf(lo.x), sly=sigf(lo.y), slz=sigf(lo.z), slw=sigf(lo.w);
    float shx=sigf(hi.x), shy=sigf(hi.y), shz=sigf(hi.z), shw=sigf(hi.w);
    int plane = rid >> 8, r = rid & 255;
    float2* row = g_pk + ((size_t)plane*PSTR + 1 + r)*PROW;
    float2* o = row + 1 + 4*q;
    o[0] = make_float2(slx, shx);
    o[1] = make_float2(sly, shy);
    o[2] = make_float2(slz, shz);
    o[3] = make_float2(slw, shw);
    if (q == 31) row[0]   = make_float2(0.f, slw);
    if (q == 0){
      row[129] = make_float2(shx, 0.f);
      row[130] = make_float2(shy, 0.f);
      row[131] = make_float2(0.f, 0.f);
    }
    return;
  }
  int z = (blockIdx.x - 1 - MAIN_BLKS)*256 + threadIdx.x;
  if (z >= PAD_F2) return;
  int plane = z / (3*PROW);
  int rem   = z - plane*(3*PROW);
  int which = rem / PROW;
  int col   = rem - which*PROW;
  int prow  = (which == 0) ? 0 : (256 + which);
  g_pk[((size_t)plane*PSTR + prow)*PROW + col] = make_float2(0.f, 0.f);
}

// ---------- conv compute helpers ----------
__device__ __forceinline__ void load5(ull (&R)[5], const ull* rows, int rowidx, int base){
  const ull* rp = rows + rowidx*PROW + base;
  ulonglong2 t0 = *(const ulonglong2*)(rp);
  ulonglong2 t1 = *(const ulonglong2*)(rp + 2);
  R[0]=t0.x; R[1]=t0.y; R[2]=t1.x; R[3]=t1.y;
  R[4]=rp[4];
}
__device__ __forceinline__ void fma_ky(ull (&acc)[3][2][4],
                                       const ull (&T)[5], const ull (&Bt)[5],
                                       const float2* wb, int ci, int ky, int mh){
  #pragma unroll
  for (int co=0; co<3; co++){
    const ulonglong2* wp = (const ulonglong2*)(wb + (co*3+ci)*16 + ky*4);
    ulonglong2 w01 = wp[0], w23 = wp[1];
    #pragma unroll
    for (int mm=0; mm<2; mm++){
      const int m = 2*mh + mm;
      acc[co][0][m] = ffma2(T[mm+0],  w01.x, acc[co][0][m]);
      acc[co][0][m] = ffma2(T[mm+1],  w01.y, acc[co][0][m]);
      acc[co][0][m] = ffma2(T[mm+2],  w23.x, acc[co][0][m]);
      acc[co][0][m] = ffma2(T[mm+3],  w23.y, acc[co][0][m]);
      acc[co][1][m] = ffma2(Bt[mm+0], w01.x, acc[co][1][m]);
      acc[co][1][m] = ffma2(Bt[mm+1], w01.y, acc[co][1][m]);
      acc[co][1][m] = ffma2(Bt[mm+2], w23.x, acc[co][1][m]);
      acc[co][1][m] = ffma2(Bt[mm+3], w23.y, acc[co][1][m]);
    }
  }
}

// ---------- pass 2: persistent conv, cross-tile streaming producer ----------
extern __shared__ __align__(16) float2 dynslot[];

__global__ void __launch_bounds__(128, 4) conv_kernel(float* __restrict__ out){
  __shared__ __align__(16) float2 w_all[4*144];
  __shared__ __align__(8) ull mbars[2*NSLOT];
  __shared__ unsigned s_next;

  const int tx  = threadIdx.x;
  const int ty  = threadIdx.y;
  const int tid = ty*32 + tx;
  const int r0  = 2*ty;

  const uint32_t slot_u32 = (uint32_t)__cvta_generic_to_shared(&dynslot[0]);
  const uint32_t mbar_u32 = (uint32_t)__cvta_generic_to_shared(&mbars[0]);
  #define FULLB(si)  (mbar_u32 + (unsigned)(si)*8u)
  #define EMPTYB(si) (mbar_u32 + 32u + (unsigned)(si)*8u)

  if (tid < NSLOT)        mbar_init(FULLB(tid), 1);
  else if (tid < 2*NSLOT) mbar_init(EMPTYB(tid-NSLOT), 4);

  unsigned ph = 0, eph = 0;     // consumer/producer per-slot parity
  unsigned P  = 0;              // base global plane index of current tile
  unsigned PW = 0;              // produced watermark (tid0 meaningful)

  int prev_v = -1;

  // Bootstrap: fetch first tile, then prefetch next.
  if (tid == 0) s_next = atomicAdd(&g_ctr, 1u);
  __syncthreads();              // also publishes mbar_init
  unsigned cur = s_next;
  __syncthreads();
  unsigned nxt_t = 0u;
  if (tid == 0){ nxt_t = atomicAdd(&g_ctr, 1u); s_next = nxt_t; }

  while (cur < NTILES){
    const int v   = (int)(cur >> 7);
    const int rem = (int)(cur & 127u);
    const int b   = rem >> 5;
    const int y0  = (rem & 31) * 8;
    const int deg = g_deg[v];
    const int S   = 3*deg;
    float bsum0 = g_bsum[v][0], bsum1 = g_bsum[v][1], bsum2 = g_bsum[v][2];

    if (v != prev_v){
      prev_v = v;
      for (int q = tid; q < deg*144; q += 128)
        w_all[q] = g_wpk[g_eid[v][q/144]*144 + (q - (q/144)*144)];
      __syncthreads();
    }

    // tid0: next-tile producer params (registers).
    int nv=0, nb=0, ny0=0; bool nxt_ok = false;
    if (tid == 0 && nxt_t < NTILES){
      nxt_ok = true;
      nv  = (int)(nxt_t >> 7);
      int nrem = (int)(nxt_t & 127u);
      nb  = nrem >> 5;
      ny0 = (nrem & 31) * 8;
    }

    ull acc[3][2][4];
    #pragma unroll
    for (int co=0; co<3; co++)
      #pragma unroll
      for (int rl=0; rl<2; rl++)
        #pragma unroll
        for (int m=0; m<4; m++) acc[co][rl][m] = 0ull;

    int wi = 0, wci = 0;
    for (int s=0; s<S; s++){
      if (tid == 0){
        const unsigned tgt = P + (unsigned)s + 3u;
        while (PW <= tgt){
          const unsigned off = PW - P;
          int li, pv, pb, py;
          if (off < (unsigned)S){ li=(int)off; pv=v; pb=b; py=y0; }
          else {
            if (!nxt_ok) break;
            li=(int)(off-(unsigned)S); pv=nv; pb=nb; py=ny0;  // li<=2 < next S
          }
          const int ii = li/3, cc2 = li - 3*ii;
          const int si = (int)(PW & 3u);
          if (PW >= 4u){ mbar_wait(EMPTYB(si), (eph>>si)&1u); eph ^= (1u<<si); }
          const int sn = __ldg(&g_esr[pv][ii]);
          const int pl = (sn*BB + pb)*CC + cc2;
          const char* sp = (const char*)g_pk + ((size_t)pl*PSTR + py)*ROWB;
          mbar_expect_tx(FULLB(si), 11u*ROWB);
          tma_bulk(slot_u32 + (uint32_t)(si*PLANE_BYTES), sp, 11u*ROWB, FULLB(si));
          PW++;
        }
      }
      const int si = (int)((P + (unsigned)s) & 3u);
      mbar_wait(FULLB(si), (ph>>si)&1u);
      ph ^= (1u<<si);

      const ull* rows  = (const ull*)&dynslot[si*PLANE_F2];
      const float2* wb = w_all + wi*144;
      const int ci = wci;

      #pragma unroll
      for (int mh=0; mh<2; mh++){
        const int base = 2*tx + 64*mh;
        ull Ra[5], Rb[5];
        load5(Ra, rows, r0,   base);
        load5(Rb, rows, r0+1, base); fma_ky(acc, Ra, Rb, wb, ci, 0, mh);
        load5(Ra, rows, r0+2, base); fma_ky(acc, Rb, Ra, wb, ci, 1, mh);
        load5(Rb, rows, r0+3, base); fma_ky(acc, Ra, Rb, wb, ci, 2, mh);
        load5(Ra, rows, r0+4, base); fma_ky(acc, Rb, Ra, wb, ci, 3, mh);
      }
      __syncwarp();
      if (tx == 0) mbar_arrive(EMPTYB(si));
      if (++wci == 3){ wci = 0; wi++; }
    }

    // Epilogue (TMA for next tile already in flight).
    const float inv = 1.f / (float)deg;
    const float bs[3] = {bsum0, bsum1, bsum2};
    #pragma unroll
    for (int co=0; co<3; co++){
      #pragma unroll
      for (int rl=0; rl<2; rl++){
        float* ob = out + (((size_t)v*BB + b)*CC + co)*HWSZ + (y0 + r0 + rl)*WW;
        #pragma unroll
        for (int mh=0; mh<2; mh++){
          float lo0, hi0, lo1, hi1;
          upk2(acc[co][rl][2*mh+0], lo0, hi0);
          upk2(acc[co][rl][2*mh+1], lo1, hi1);
          int x = 2*tx + 64*mh;
          *(float2*)(ob + x)       = make_float2((lo0+bs[co])*inv, (lo1+bs[co])*inv);
          *(float2*)(ob + x + 128) = make_float2((hi0+bs[co])*inv, (hi1+bs[co])*inv);
        }
      }
    }

    P += (unsigned)S;
    __syncthreads();            // A: everyone done with this tile
    cur = s_next;               // advance to prefetched tile
    __syncthreads();            // B: reads done before tid0 overwrites
    if (tid == 0){ nxt_t = atomicAdd(&g_ctr, 1u); s_next = nxt_t; }
  }
}

extern "C" void kernel_launch(void* const* d_in, const int* in_sizes, int n_in,
                              void* d_out, int out_size){
  const float* states  = (const float*)d_in[0];
  const float* weights = (const float*)d_in[1];
  const float* bias    = (const float*)d_in[2];
  const int*   esrc    = (const int*)d_in[3];
  const int*   edst    = (const int*)d_in[4];
  float*       out     = (float*)d_out;

  sigmoid_pack_all<<<1 + MAIN_BLKS + PAD_BLKS, 256>>>(states, weights, bias, esrc, edst);

  static int smem_set = 0;
  if (!smem_set){
    cudaFuncSetAttribute(conv_kernel, cudaFuncAttributeMaxDynamicSharedMemorySize,
                         DYN_BYTES);
    smem_set = 1;
  }
  conv_kernel<<<NCTA, dim3(32,4), DYN_BYTES>>>(out);
}